// round 1
// baseline (speedup 1.0000x reference)
#include <cuda_runtime.h>
#include <cuda_bf16.h>

// Sparsity_60095182405891: x[64,256,56,56] f32, NCHW.
// mask1: keep top-2 (ties >=) of |x| per 4-channel block.
// mask2: zero kept, keep top-1 (ties >=) of residual per 8-channel block.
// out = x * (mask1 | mask2).
//
// Decomposition: each thread owns one (n, 8-channel group, float4-of-w) tile:
// 8 independent LDG.128 (MLP=8), register-resident mask math, 8 STG.128.
// Pure HBM-bound streaming: 411 MB total traffic -> ~51 us floor @ 8 TB/s.

#define C_TOT   256
#define HW      3136            // 56*56
#define GROUPS  (C_TOT / 8)     // 32
#define VEC     (HW / 4)        // 784
#define NTOTAL  (64 * GROUPS * VEC)   // 1,605,632 threads

__device__ __forceinline__ float second_of_4(float a0, float a1, float a2, float a3) {
    // 2nd largest of 4 (tournament): max( min(max01, max23), max(min01, min23) )
    float m01 = fmaxf(a0, a1), n01 = fminf(a0, a1);
    float m23 = fmaxf(a2, a3), n23 = fminf(a2, a3);
    return fmaxf(fminf(m01, m23), fmaxf(n01, n23));
}

__global__ void __launch_bounds__(256)
sparsity_nm_kernel(const float* __restrict__ x, float* __restrict__ out) {
    int tid = blockIdx.x * blockDim.x + threadIdx.x;
    if (tid >= NTOTAL) return;

    int p = tid % VEC;          // which float4 within the 56x56 plane
    int t = tid / VEC;
    int g = t % GROUPS;         // which 8-channel group
    int n = t / GROUPS;         // which image

    long base = ((long)(n * C_TOT + g * 8)) * HW + (long)p * 4;

    const float4* xin = reinterpret_cast<const float4*>(x + base);
    float4*       xo  = reinterpret_cast<float4*>(out + base);

    // 8 independent strided vector loads (stride HW floats = 12544 B)
    float4 v[8];
#pragma unroll
    for (int c = 0; c < 8; c++) {
        v[c] = xin[(long)c * (HW / 4)];
    }

    // Unpack to [channel][lane] register array (fully unrolled -> stays in regs)
    float val[8][4];
#pragma unroll
    for (int c = 0; c < 8; c++) {
        val[c][0] = v[c].x; val[c][1] = v[c].y;
        val[c][2] = v[c].z; val[c][3] = v[c].w;
    }

#pragma unroll
    for (int l = 0; l < 4; l++) {
        float a[8];
#pragma unroll
        for (int c = 0; c < 8; c++) a[c] = fabsf(val[c][l]);

        // mask1: top-2 (ties kept) within each 4-channel block
        float thr0 = second_of_4(a[0], a[1], a[2], a[3]);
        float thr1 = second_of_4(a[4], a[5], a[6], a[7]);

        bool  m1[8];
        float r[8];
        float rmax = 0.0f;
#pragma unroll
        for (int c = 0; c < 8; c++) {
            float thr = (c < 4) ? thr0 : thr1;
            m1[c] = (a[c] >= thr);
            r[c]  = m1[c] ? 0.0f : a[c];
            rmax  = fmaxf(rmax, r[c]);
        }

        // mask2: top-1 (ties kept) of residual over the 8-block; OR with mask1
#pragma unroll
        for (int c = 0; c < 8; c++) {
            bool keep = m1[c] || (r[c] >= rmax);
            val[c][l] = keep ? val[c][l] : 0.0f;
        }
    }

    // Repack and store
#pragma unroll
    for (int c = 0; c < 8; c++) {
        float4 o;
        o.x = val[c][0]; o.y = val[c][1]; o.z = val[c][2]; o.w = val[c][3];
        xo[(long)c * (HW / 4)] = o;
    }
}

extern "C" void kernel_launch(void* const* d_in, const int* in_sizes, int n_in,
                              void* d_out, int out_size) {
    const float* x = (const float*)d_in[0];
    float* out = (float*)d_out;
    int blocks = (NTOTAL + 255) / 256;   // 6272
    sparsity_nm_kernel<<<blocks, 256>>>(x, out);
}